// round 1
// baseline (speedup 1.0000x reference)
#include <cuda_runtime.h>
#include <cstdint>
#include <cfloat>

#define NU 100000
#define NI 50000
#define DIM 128
#define EU 400000
#define EI 200000
#define BATCH 4096

// ---------------- scratch (static device memory; no allocs allowed) ----------
__device__ float g_h[NU * DIM];        // h = act(x) @ W        (51.2 MB)
__device__ float g_out1[NU * DIM];     // layer-1 aggregate     (51.2 MB)
__device__ float g_uout2[NU * DIM];    // user layer-2 output   (51.2 MB)
__device__ float g_iout2[NI * DIM];    // item layer-2 output   (25.6 MB)
__device__ float g_ssrc[NU];
__device__ float g_sdst[NU];
__device__ float g_m[NU];
__device__ float g_denom[NU];
__device__ float g_elog[EU];

// ---------------- helpers ----------------------------------------------------
__device__ __forceinline__ float elu_f(float x) { return x > 0.f ? x : expm1f(x); }

__device__ __forceinline__ unsigned long long dup2(float x) {
    unsigned long long r; asm("mov.b64 %0, {%1, %1};" : "=l"(r) : "f"(x)); return r;
}
__device__ __forceinline__ unsigned long long pack2(float a, float b) {
    unsigned long long r; asm("mov.b64 %0, {%1, %2};" : "=l"(r) : "f"(a), "f"(b)); return r;
}
__device__ __forceinline__ void unpack2(unsigned long long v, float& a, float& b) {
    asm("mov.b64 {%0, %1}, %2;" : "=f"(a), "=f"(b) : "l"(v));
}
__device__ __forceinline__ void ffma2(unsigned long long& d, unsigned long long a, unsigned long long b) {
    asm("fma.rn.f32x2 %0, %1, %2, %0;" : "+l"(d) : "l"(a), "l"(b));
}
__device__ __forceinline__ void atomicMaxFloat(float* addr, float v) {
    if (v >= 0.f) atomicMax((int*)addr, __float_as_int(v));
    else          atomicMin((unsigned int*)addr, __float_as_uint(v));
}
__device__ __forceinline__ void red_add_v4(float* addr, float4 v) {
    asm volatile("red.global.add.v4.f32 [%0], {%1, %2, %3, %4};"
                 :: "l"(addr), "f"(v.x), "f"(v.y), "f"(v.z), "f"(v.w) : "memory");
}

// ---------------- init: zero out-accumulator + softmax state -----------------
__global__ void init_kernel(float* __restrict__ out, float* __restrict__ m,
                            float* __restrict__ den, int N) {
    int i = blockIdx.x * blockDim.x + threadIdx.x;
    if (i < N * DIM) out[i] = 0.f;
    if (i < N) { m[i] = -FLT_MAX; den[i] = 0.f; }
}

// ---------------- fused GEMM + attention scalars ------------------------------
// h[r][c] = sum_k act(x[r][k]) * W[k][c];  s_src[r]=h[r]·a_src;  s_dst[r]=h[r]·a_dst
// 128-row block tile, full 128-col width. 256 threads, 8x8 register tile, f32x2.
template <int ACT>
__global__ void __launch_bounds__(256) gemm_attn_kernel(
    const float* __restrict__ x, const float* __restrict__ W,
    const float* __restrict__ a_src, const float* __restrict__ a_dst,
    float* __restrict__ h, float* __restrict__ ssrc, float* __restrict__ sdst, int N)
{
    extern __shared__ float smem[];
    float* ws = smem;               // 128*128 floats (64 KB)
    float* xs = smem + 128 * 128;   // 32*132 floats  (transposed x chunk, padded)

    const int tid = threadIdx.x;
    const int tx = tid & 15;        // column group (8 cols)
    const int ty = tid >> 4;        // row group (8 rows)
    const int r0 = blockIdx.x * 128;

    // stage full W in smem
#pragma unroll
    for (int i = 0; i < 16; ++i) {
        int idx = (tid + i * 256) * 4;
        *(float4*)&ws[idx] = *(const float4*)&W[idx];
    }

    unsigned long long acc[8][4];
#pragma unroll
    for (int r = 0; r < 8; ++r)
#pragma unroll
        for (int c = 0; c < 4; ++c) acc[r][c] = 0ull;

    for (int kc = 0; kc < 4; ++kc) {
        __syncthreads();
        // load x chunk (128 rows x 32 k), transposed into xs[k][row], stride 132
#pragma unroll
        for (int i = 0; i < 4; ++i) {
            int li = tid + i * 256;
            int row = li >> 3;
            int kq = li & 7;
            float4 v = make_float4(0.f, 0.f, 0.f, 0.f);
            if (r0 + row < N)
                v = *(const float4*)&x[(size_t)(r0 + row) * DIM + kc * 32 + kq * 4];
            if (ACT) { v.x = elu_f(v.x); v.y = elu_f(v.y); v.z = elu_f(v.z); v.w = elu_f(v.w); }
            xs[(kq * 4 + 0) * 132 + row] = v.x;
            xs[(kq * 4 + 1) * 132 + row] = v.y;
            xs[(kq * 4 + 2) * 132 + row] = v.z;
            xs[(kq * 4 + 3) * 132 + row] = v.w;
        }
        __syncthreads();
#pragma unroll
        for (int k = 0; k < 32; ++k) {
            const int kg = kc * 32 + k;
            float4 wA = *(const float4*)&ws[kg * 128 + tx * 8];
            float4 wB = *(const float4*)&ws[kg * 128 + tx * 8 + 4];
            unsigned long long w0 = pack2(wA.x, wA.y);
            unsigned long long w1 = pack2(wA.z, wA.w);
            unsigned long long w2 = pack2(wB.x, wB.y);
            unsigned long long w3 = pack2(wB.z, wB.w);
            float4 xA = *(const float4*)&xs[k * 132 + ty * 8];
            float4 xB = *(const float4*)&xs[k * 132 + ty * 8 + 4];
            float xr[8] = {xA.x, xA.y, xA.z, xA.w, xB.x, xB.y, xB.z, xB.w};
#pragma unroll
            for (int r = 0; r < 8; ++r) {
                unsigned long long xd = dup2(xr[r]);
                ffma2(acc[r][0], xd, w0);
                ffma2(acc[r][1], xd, w1);
                ffma2(acc[r][2], xd, w2);
                ffma2(acc[r][3], xd, w3);
            }
        }
    }

    // epilogue: store h, accumulate per-thread partial dots with a_src/a_dst
    float asr[8], adr[8];
#pragma unroll
    for (int c = 0; c < 8; ++c) { asr[c] = a_src[tx * 8 + c]; adr[c] = a_dst[tx * 8 + c]; }

    float psrc[8], pdst[8];
#pragma unroll
    for (int r = 0; r < 8; ++r) {
        float hv[8];
        unpack2(acc[r][0], hv[0], hv[1]);
        unpack2(acc[r][1], hv[2], hv[3]);
        unpack2(acc[r][2], hv[4], hv[5]);
        unpack2(acc[r][3], hv[6], hv[7]);
        int row = r0 + ty * 8 + r;
        if (row < N) {
            *(float4*)&h[(size_t)row * DIM + tx * 8]     = make_float4(hv[0], hv[1], hv[2], hv[3]);
            *(float4*)&h[(size_t)row * DIM + tx * 8 + 4] = make_float4(hv[4], hv[5], hv[6], hv[7]);
        }
        float ps = 0.f, pd = 0.f;
#pragma unroll
        for (int c = 0; c < 8; ++c) { ps += hv[c] * asr[c]; pd += hv[c] * adr[c]; }
        psrc[r] = ps; pdst[r] = pd;
    }

    // deterministic block reduction over the 16 column-group threads
    __syncthreads();
#pragma unroll
    for (int r = 0; r < 8; ++r) xs[(ty * 8 + r) * 16 + tx] = psrc[r];
    __syncthreads();
    if (tid < 128) {
        int row = r0 + tid;
        if (row < N) {
            float s = 0.f;
#pragma unroll
            for (int i = 0; i < 16; ++i) s += xs[tid * 16 + i];
            ssrc[row] = s;
        }
    }
    __syncthreads();
#pragma unroll
    for (int r = 0; r < 8; ++r) xs[(ty * 8 + r) * 16 + tx] = pdst[r];
    __syncthreads();
    if (tid < 128) {
        int row = r0 + tid;
        if (row < N) {
            float s = 0.f;
#pragma unroll
            for (int i = 0; i < 16; ++i) s += xs[tid * 16 + i];
            sdst[row] = s;
        }
    }
}

// ---------------- edge pass 1: leaky-relu logits + segment max ----------------
__global__ void edge_logits_kernel(const int* __restrict__ src, const int* __restrict__ dst,
                                   const float* __restrict__ ssrc, const float* __restrict__ sdst,
                                   float* __restrict__ elog, float* __restrict__ m, int E)
{
    int e = blockIdx.x * blockDim.x + threadIdx.x;
    if (e < E) {
        int d = dst[e];
        float l = ssrc[src[e]] + sdst[d];
        l = l > 0.f ? l : 0.2f * l;
        elog[e] = l;
        atomicMaxFloat(m + d, l);
    }
}

// ---------------- edge pass 2: exp + segment sum ------------------------------
__global__ void edge_exp_kernel(const int* __restrict__ dst, float* __restrict__ elog,
                                const float* __restrict__ m, const float* __restrict__ ev,
                                float* __restrict__ den, int E)
{
    int e = blockIdx.x * blockDim.x + threadIdx.x;
    if (e < E) {
        int d = dst[e];
        float v = expf(elog[e] - m[d]) * ev[e];
        elog[e] = v;
        atomicAdd(den + d, v);
    }
}

// ---------------- edge pass 3: scatter-add h[src]*coef into out[dst] ----------
// one warp per edge; lane handles 4 contiguous floats; vector RED (v4.f32)
__global__ void edge_aggregate_kernel(const int* __restrict__ src, const int* __restrict__ dst,
                                      const float* __restrict__ eval, const float* __restrict__ den,
                                      const float* __restrict__ h, float* __restrict__ out, int E)
{
    int lane = threadIdx.x & 31;
    int warp = (blockIdx.x * blockDim.x + threadIdx.x) >> 5;
    int nwarp = (gridDim.x * blockDim.x) >> 5;
    for (int e = warp; e < E; e += nwarp) {
        int s = src[e], d = dst[e];
        float coef = eval[e] / (den[d] + 1e-16f);
        float4 v = *(const float4*)(h + (size_t)s * DIM + lane * 4);
        v.x *= coef; v.y *= coef; v.z *= coef; v.w *= coef;
        red_add_v4(out + (size_t)d * DIM + lane * 4, v);
    }
}

// ---------------- final gather (elu applied here) -----------------------------
__global__ void gather_kernel(const float* __restrict__ uo, const float* __restrict__ io,
                              const int* __restrict__ uid, const int* __restrict__ iid,
                              float* __restrict__ out)
{
    int t = blockIdx.x * blockDim.x + threadIdx.x;
    int b = t >> 7, c = t & 127;
    if (b < BATCH)            out[t] = elu_f(uo[(size_t)uid[b] * DIM + c]);
    else if (b < 2 * BATCH)   out[t] = elu_f(io[(size_t)iid[b - BATCH] * DIM + c]);
}

// ---------------- host orchestration -----------------------------------------
static void run_layer(const float* x, int act, const int* ei, const float* ev, int E, int N,
                      const float* W, const float* as, const float* ad,
                      float* h, float* outp, float* ssrc, float* sdst,
                      float* m, float* den, float* elog, int smem)
{
    const int TB = 256;
    init_kernel<<<(N * DIM + TB - 1) / TB, TB>>>(outp, m, den, N);
    if (act)
        gemm_attn_kernel<1><<<(N + 127) / 128, 256, smem>>>(x, W, as, ad, h, ssrc, sdst, N);
    else
        gemm_attn_kernel<0><<<(N + 127) / 128, 256, smem>>>(x, W, as, ad, h, ssrc, sdst, N);
    const int* src = ei;
    const int* dst = ei + E;
    edge_logits_kernel<<<(E + TB - 1) / TB, TB>>>(src, dst, ssrc, sdst, elog, m, E);
    edge_exp_kernel<<<(E + TB - 1) / TB, TB>>>(dst, elog, m, ev, den, E);
    edge_aggregate_kernel<<<2048, 256>>>(src, dst, elog, den, h, outp, E);
}

extern "C" void kernel_launch(void* const* d_in, const int* in_sizes, int n_in,
                              void* d_out, int out_size)
{
    const int*   uedg = (const int*)d_in[0];
    const int*   iedg = (const int*)d_in[1];
    const int*   user_id = (const int*)d_in[2];
    const int*   item_id = (const int*)d_in[3];
    const float* uval = (const float*)d_in[4];
    const float* ival = (const float*)d_in[5];
    const float* umat = (const float*)d_in[6];
    const float* imat = (const float*)d_in[7];
    const float* W_u1 = (const float*)d_in[8];
    const float* as_u1 = (const float*)d_in[9];
    const float* ad_u1 = (const float*)d_in[10];
    const float* W_u2 = (const float*)d_in[11];
    const float* as_u2 = (const float*)d_in[12];
    const float* ad_u2 = (const float*)d_in[13];
    const float* W_i1 = (const float*)d_in[14];
    const float* as_i1 = (const float*)d_in[15];
    const float* ad_i1 = (const float*)d_in[16];
    const float* W_i2 = (const float*)d_in[17];
    const float* as_i2 = (const float*)d_in[18];
    const float* ad_i2 = (const float*)d_in[19];

    float *h, *out1, *uout2, *iout2, *ssrc, *sdst, *m, *den, *elog;
    cudaGetSymbolAddress((void**)&h, g_h);
    cudaGetSymbolAddress((void**)&out1, g_out1);
    cudaGetSymbolAddress((void**)&uout2, g_uout2);
    cudaGetSymbolAddress((void**)&iout2, g_iout2);
    cudaGetSymbolAddress((void**)&ssrc, g_ssrc);
    cudaGetSymbolAddress((void**)&sdst, g_sdst);
    cudaGetSymbolAddress((void**)&m, g_m);
    cudaGetSymbolAddress((void**)&den, g_denom);
    cudaGetSymbolAddress((void**)&elog, g_elog);

    const int smem = (128 * 128 + 32 * 132) * (int)sizeof(float);
    cudaFuncSetAttribute(gemm_attn_kernel<0>, cudaFuncAttributeMaxDynamicSharedMemorySize, smem);
    cudaFuncSetAttribute(gemm_attn_kernel<1>, cudaFuncAttributeMaxDynamicSharedMemorySize, smem);

    // item chain
    run_layer(imat, 0, iedg, ival, EI, NI, W_i1, as_i1, ad_i1, h, out1, ssrc, sdst, m, den, elog, smem);
    run_layer(out1, 1, iedg, ival, EI, NI, W_i2, as_i2, ad_i2, h, iout2, ssrc, sdst, m, den, elog, smem);
    // user chain (reuses out1 / h scratch)
    run_layer(umat, 0, uedg, uval, EU, NU, W_u1, as_u1, ad_u1, h, out1, ssrc, sdst, m, den, elog, smem);
    run_layer(out1, 1, uedg, uval, EU, NU, W_u2, as_u2, ad_u2, h, uout2, ssrc, sdst, m, den, elog, smem);

    gather_kernel<<<(2 * BATCH * DIM) / 256, 256>>>(uout2, iout2, user_id, item_id, (float*)d_out);
}